// round 1
// baseline (speedup 1.0000x reference)
#include <cuda_runtime.h>
#include <stdint.h>

// PicMix: output is two index-function masks, no input data needed.
// Layout (flattened tuple): [mask_a (8,12,512,512) fp32][mask_b same].
// Per-plane (512x512) value depends only on (maskSel, ch%12 -> group, i%2, j%2):
//   g0: a=1, b=0
//   g1 (ABA):     a = (i%2==j%2), b = complement
//   g2 (AAA-BBB): a = i%2,        b = 1-i%2
//   g3 (AAA|BBB): a = j%2,        b = 1-j%2
// Each thread writes one float4 (4 consecutive j, starting at even j), so the
// lane values are just an (even-lane, odd-lane) pair.

static constexpr int H = 512;
static constexpr int W = 512;
static constexpr int PLANE_F4 = (H * W) / 4;   // 65536 float4 per plane
static constexpr int ROW_F4 = W / 4;           // 128 float4 per row

__global__ void __launch_bounds__(256) picmix_kernel(float4* __restrict__ out, int total4) {
    int idx = blockIdx.x * blockDim.x + threadIdx.x;
    if (idx >= total4) return;

    int plane  = idx >> 16;          // PLANE_F4 = 2^16
    int within = idx & (PLANE_F4 - 1);
    int i      = within >> 7;        // ROW_F4 = 2^7
    int ip     = i & 1;

    int isB = plane >= 96;           // 96 planes per mask (8 batch * 12 ch)
    int pin = plane - (isB ? 96 : 0);
    int ch  = pin % 12;
    int g   = ch * 0x5556 >> 16;     // ch/3 for ch in [0,12): exact via fixed-point

    float e, o;                      // even-lane value, odd-lane value
    if (g == 0) {
        e = o = isB ? 0.0f : 1.0f;
    } else if (g == 1) {
        // a: even lane = (i even), odd lane = (i odd); b: swapped
        float s = (ip == 0) ? 1.0f : 0.0f;
        e = isB ? 1.0f - s : s;
        o = 1.0f - e;
    } else if (g == 2) {
        float v = (float)ip;
        e = o = isB ? 1.0f - v : v;
    } else {
        // a: j%2 -> {0,1}; b: {1,0}
        e = isB ? 1.0f : 0.0f;
        o = 1.0f - e;
    }

    out[idx] = make_float4(e, o, e, o);
}

extern "C" void kernel_launch(void* const* d_in, const int* in_sizes, int n_in,
                              void* d_out, int out_size) {
    (void)d_in; (void)in_sizes; (void)n_in;
    int total4 = out_size / 4;       // out_size = 50,331,648 fp32 -> 12,582,912 float4
    int threads = 256;
    int blocks = (total4 + threads - 1) / threads;
    picmix_kernel<<<blocks, threads>>>((float4*)d_out, total4);
}